// round 2
// baseline (speedup 1.0000x reference)
#include <cuda_runtime.h>

// out[b, j] = prod_{k<=j} cos(x[b,k]) * cos(params[k])
// Derivation: product state after RX/RY layers; CNOT chain maps Z_j -> Z_0...Z_j
// in the Heisenberg picture; single-qubit <Z> after RY(p)RX(x)|0> = cos(p)cos(x).

#define N_WIRES 10

__global__ __launch_bounds__(128) void _QuantumGate_65481071395894_kernel(
    const float* __restrict__ x,      // (B, 10)
    const float* __restrict__ params, // (10,)
    float* __restrict__ out,          // (B, 10)
    int B)
{
    int b = blockIdx.x * blockDim.x + threadIdx.x;
    if (b >= B) return;

    // cos(params) — broadcast via L1/L2, negligible cost
    float cp[N_WIRES];
#pragma unroll
    for (int k = 0; k < N_WIRES; k++) cp[k] = cosf(__ldg(params + k));

    // Row is 40 bytes, always 8-byte aligned -> 5x float2 loads
    const float2* xr = reinterpret_cast<const float2*>(x + (size_t)b * N_WIRES);
    float xv[N_WIRES];
#pragma unroll
    for (int i = 0; i < 5; i++) {
        float2 v = __ldg(xr + i);
        xv[2 * i]     = v.x;
        xv[2 * i + 1] = v.y;
    }

    float r = 1.0f;
    float o[N_WIRES];
#pragma unroll
    for (int k = 0; k < N_WIRES; k++) {
        r *= cosf(xv[k]) * cp[k];
        o[k] = r;
    }

    float2* orow = reinterpret_cast<float2*>(out + (size_t)b * N_WIRES);
#pragma unroll
    for (int i = 0; i < 5; i++) {
        orow[i] = make_float2(o[2 * i], o[2 * i + 1]);
    }
}

extern "C" void kernel_launch(void* const* d_in, const int* in_sizes, int n_in,
                              void* d_out, int out_size) {
    const float* x      = (const float*)d_in[0];   // (16384, 10) float32
    const float* params = (const float*)d_in[1];   // (10,) float32
    float* out          = (float*)d_out;           // (16384, 10) float32

    int B = in_sizes[0] / N_WIRES;
    int threads = 128;
    int blocks = (B + threads - 1) / threads;
    _QuantumGate_65481071395894_kernel<<<blocks, threads>>>(x, params, out, B);
}

// round 4
// speedup vs baseline: 1.1212x; 1.1212x over previous
#include <cuda_runtime.h>

// out[b, j] = prod_{k<=j} cos(x[b,k]) * cos(params[k])
// Closed form of the circuit: product state after RX/RY layers; CNOT chain maps
// Z_j -> Z_0...Z_j (Heisenberg); single-qubit <Z> after RY(p)RX(x)|0> = cos(p)cos(x).

#define N_WIRES 10

__global__ __launch_bounds__(64) void _QuantumGate_65481071395894_kernel(
    const float* __restrict__ x,      // (B, 10)
    const float* __restrict__ params, // (10,)
    float* __restrict__ out,          // (B, 10)
    int B)
{
    int b = blockIdx.x * blockDim.x + threadIdx.x;
    if (b >= B) return;

    // cos(params): 10 broadcast loads (L2-hit after first warp) + 10 MUFU
    float cp[N_WIRES];
#pragma unroll
    for (int k = 0; k < N_WIRES; k++) cp[k] = __cosf(__ldg(params + k));

    // Row = 40 bytes, 8-byte aligned -> 5x LDG.64, issued back-to-back (MLP=5)
    const float2* xr = reinterpret_cast<const float2*>(x + (size_t)b * N_WIRES);
    float xv[N_WIRES];
#pragma unroll
    for (int i = 0; i < 5; i++) {
        float2 v = __ldg(xr + i);
        xv[2 * i]     = v.x;
        xv[2 * i + 1] = v.y;
    }

    // All 10 __cosf are independent (pipeline through MUFU), then a 10-deep
    // multiply chain (4cyc each) for the prefix product.
    float c[N_WIRES];
#pragma unroll
    for (int k = 0; k < N_WIRES; k++) c[k] = __cosf(xv[k]) * cp[k];

    float r = 1.0f;
    float o[N_WIRES];
#pragma unroll
    for (int k = 0; k < N_WIRES; k++) {
        r *= c[k];
        o[k] = r;
    }

    float2* orow = reinterpret_cast<float2*>(out + (size_t)b * N_WIRES);
#pragma unroll
    for (int i = 0; i < 5; i++) {
        orow[i] = make_float2(o[2 * i], o[2 * i + 1]);
    }
}

extern "C" void kernel_launch(void* const* d_in, const int* in_sizes, int n_in,
                              void* d_out, int out_size) {
    const float* x      = (const float*)d_in[0];   // (16384, 10) float32
    const float* params = (const float*)d_in[1];   // (10,) float32
    float* out          = (float*)d_out;           // (16384, 10) float32

    int B = in_sizes[0] / N_WIRES;      // 16384
    int threads = 64;                   // 256 blocks -> all 148+ SMs covered
    int blocks = (B + threads - 1) / threads;
    _QuantumGate_65481071395894_kernel<<<blocks, threads>>>(x, params, out, B);
}